// round 7
// baseline (speedup 1.0000x reference)
#include <cuda_runtime.h>
#include <cuda_bf16.h>

#define NUSERS 100000
#define NITEMS 200000
#define DIM    128
#define NEDGES 2000000
#define LN_EPS 1e-5f

#define NBUCKETS (NUSERS + NITEMS)
#define RSV_BLK 1024
#define NU_BLKS ((NUSERS + RSV_BLK - 1) / RSV_BLK)   // 98
#define NC_BLKS ((NITEMS + RSV_BLK - 1) / RSV_BLK)   // 196

// ---------------- scratch (device globals; no allocations allowed) ----------
// NOTE: device globals are zero-initialized at module load. g_cnt/g_total rely
// on a self-restoring invariant: reserve_kernel re-zeroes g_cnt after reading,
// build_kernel re-zeroes g_total, so every kernel_launch call sees them zero.
__device__ __align__(16) float g_u_buf [NUSERS * DIM];   // layer-1 user out (fp32)
__device__ __align__(16) float g_i_buf [NITEMS * DIM];   // layer-1 item out (fp32)

// bf16 gather tables, word-addressed: word w of row r (dims 2w,2w+1) at r*64+w
__device__ __align__(16) unsigned int g_u_bf0[NUSERS * 64];
__device__ __align__(16) unsigned int g_i_bf0[NITEMS * 64];
__device__ __align__(16) unsigned int g_u_bf1[NUSERS * 64];
__device__ __align__(16) unsigned int g_i_bf1[NITEMS * 64];

// AoS edge lists sorted by bucket key: (other index, value-bits)
__device__ __align__(16) int2 g_by_r[NEDGES];
__device__ __align__(16) int2 g_by_c[NEDGES];

__device__ int g_cnt[NBUCKETS];    // histogram (zero on entry, restored by reserve)
__device__ int g_beg[NBUCKETS];    // per-bucket start
__device__ int g_cur[NBUCKETS];    // build cursors; after build = bucket end
__device__ int g_total[2];         // reservation counters (restored by build)

// ---------------- K1: bf16 conversion + histogram (fused) ---------------------
__global__ void prep_hist_kernel(const float4* __restrict__ u_src,
                                 const float4* __restrict__ i_src,
                                 const int* __restrict__ rows,
                                 const int* __restrict__ cols) {
    int idx = blockIdx.x * blockDim.x + threadIdx.x;
    if (idx < NUSERS * 32) {
        float4 v = __ldg(&u_src[idx]);
        __nv_bfloat162 lo = __float22bfloat162_rn(make_float2(v.x, v.y));
        __nv_bfloat162 hi = __float22bfloat162_rn(make_float2(v.z, v.w));
        uint2 o;
        o.x = *reinterpret_cast<unsigned int*>(&lo);
        o.y = *reinterpret_cast<unsigned int*>(&hi);
        reinterpret_cast<uint2*>(g_u_bf0)[idx] = o;
    }
    if (idx < NITEMS * 32) {
        float4 v = __ldg(&i_src[idx]);
        __nv_bfloat162 lo = __float22bfloat162_rn(make_float2(v.x, v.y));
        __nv_bfloat162 hi = __float22bfloat162_rn(make_float2(v.z, v.w));
        uint2 o;
        o.x = *reinterpret_cast<unsigned int*>(&lo);
        o.y = *reinterpret_cast<unsigned int*>(&hi);
        reinterpret_cast<uint2*>(g_i_bf0)[idx] = o;
    }
    if (idx < NEDGES) {
        atomicAdd(&g_cnt[__ldg(&rows[idx])], 1);
        atomicAdd(&g_cnt[NUSERS + __ldg(&cols[idx])], 1);
    }
}

// ---------------- K2: reservation scan; restores g_cnt=0 ----------------------
__global__ void reserve_kernel() {
    __shared__ int s[RSV_BLK];
    __shared__ int sbase;
    bool is_u = blockIdx.x < NU_BLKS;
    int first = is_u ? blockIdx.x * RSV_BLK
                     : NUSERS + (blockIdx.x - NU_BLKS) * RSV_BLK;
    int limit = is_u ? NUSERS : NBUCKETS;
    int t = threadIdx.x;
    int idx = first + t;
    int v = (idx < limit) ? g_cnt[idx] : 0;
    s[t] = v;
    __syncthreads();
    for (int o = 1; o < RSV_BLK; o <<= 1) {
        int x = (t >= o) ? s[t - o] : 0;
        __syncthreads();
        s[t] += x;
        __syncthreads();
    }
    if (t == RSV_BLK - 1) sbase = atomicAdd(&g_total[is_u ? 0 : 1], s[t]);
    __syncthreads();
    if (idx < limit) {
        int b = sbase + s[t] - v;
        g_beg[idx] = b;
        g_cur[idx] = b;
        g_cnt[idx] = 0;            // restore invariant for the next call
    }
}

// ---------------- K3: build AoS edge lists; restores g_total=0 -----------------
__global__ void build_kernel(const int* __restrict__ rows,
                             const int* __restrict__ cols,
                             const float* __restrict__ vals) {
    int e = blockIdx.x * blockDim.x + threadIdx.x;
    if (blockIdx.x == 0 && threadIdx.x < 2) g_total[threadIdx.x] = 0;
    if (e >= NEDGES) return;
    int r = rows[e];
    int c = cols[e];
    int vb = __float_as_int(vals[e]);
    int p1 = atomicAdd(&g_cur[r], 1);
    g_by_r[p1] = make_int2(c, vb);
    int p2 = atomicAdd(&g_cur[NUSERS + c], 1);
    g_by_c[p2] = make_int2(r, vb);
}

// ---------------- bf16x2 FMA ---------------------------------------------------
__device__ __forceinline__ void bf2_fma(float& a, float& b, unsigned int q, float v) {
    float2 f = __bfloat1622float2(*reinterpret_cast<__nv_bfloat162*>(&q));
    a += v * f.x;
    b += v * f.y;
}

// ---------------- fused layer: split-line gather + residual + LN ---------------
// Warp per destination row. Each gather row (256B bf16) is fetched with TWO
// independent 32-lane LDG.32s (lo/hi 128B halves) -> 1 cache line per LDG
// -> 1 L1tex wavefront per LDG at the fast cross-LDG rate.
// Lane l holds dims {2l, 2l+1} (lo) and {64+2l, 65+2l} (hi).
template <bool WRITE_BF>
__global__ void __launch_bounds__(256) layer_kernel(
        const float2* __restrict__ self_u,
        const float2* __restrict__ self_i,
        const unsigned int* __restrict__ bf_u,
        const unsigned int* __restrict__ bf_i,
        const float* __restrict__ gamma,
        const float* __restrict__ beta,
        float2* __restrict__ out_u,
        float2* __restrict__ out_i,
        unsigned int* __restrict__ outbf_u,
        unsigned int* __restrict__ outbf_i) {
    int w    = (blockIdx.x * blockDim.x + threadIdx.x) >> 5;
    int lane = threadIdx.x & 31;
    if (w >= NUSERS + NITEMS) return;

    const float2*       self2;
    const unsigned int* other;
    const int2*         edges;
    float2*             out2;
    unsigned int*       outbf;
    int row;
    if (w < NUSERS) {
        row   = w;
        self2 = self_u;  other = bf_i;  edges = g_by_r;
        out2  = out_u;   outbf = outbf_u;
    } else {
        row   = w - NUSERS;
        self2 = self_i;  other = bf_u;  edges = g_by_c;
        out2  = out_i;   outbf = outbf_i;
    }
    int beg = __ldg(&g_beg[w]);
    int end = __ldg(&g_cur[w]);    // post-build cursor = bucket end

    float a0 = 0.f, a1 = 0.f, a2 = 0.f, a3 = 0.f;

    int p = beg;
#pragma unroll 1
    for (; p + 4 <= end; p += 4) {
        int2 e0 = __ldg(&edges[p + 0]);
        int2 e1 = __ldg(&edges[p + 1]);
        int2 e2 = __ldg(&edges[p + 2]);
        int2 e3 = __ldg(&edges[p + 3]);
        unsigned int lo0 = __ldg(&other[e0.x * 64 + lane]);
        unsigned int hi0 = __ldg(&other[e0.x * 64 + 32 + lane]);
        unsigned int lo1 = __ldg(&other[e1.x * 64 + lane]);
        unsigned int hi1 = __ldg(&other[e1.x * 64 + 32 + lane]);
        unsigned int lo2 = __ldg(&other[e2.x * 64 + lane]);
        unsigned int hi2 = __ldg(&other[e2.x * 64 + 32 + lane]);
        unsigned int lo3 = __ldg(&other[e3.x * 64 + lane]);
        unsigned int hi3 = __ldg(&other[e3.x * 64 + 32 + lane]);
        float v0 = __int_as_float(e0.y);
        float v1 = __int_as_float(e1.y);
        float v2 = __int_as_float(e2.y);
        float v3 = __int_as_float(e3.y);
        bf2_fma(a0, a1, lo0, v0);  bf2_fma(a2, a3, hi0, v0);
        bf2_fma(a0, a1, lo1, v1);  bf2_fma(a2, a3, hi1, v1);
        bf2_fma(a0, a1, lo2, v2);  bf2_fma(a2, a3, hi2, v2);
        bf2_fma(a0, a1, lo3, v3);  bf2_fma(a2, a3, hi3, v3);
    }
    for (; p < end; p++) {
        int2 e0 = __ldg(&edges[p]);
        unsigned int lo0 = __ldg(&other[e0.x * 64 + lane]);
        unsigned int hi0 = __ldg(&other[e0.x * 64 + 32 + lane]);
        float v0 = __int_as_float(e0.y);
        bf2_fma(a0, a1, lo0, v0);  bf2_fma(a2, a3, hi0, v0);
    }

    // residual (fp32, evict-first): lane l gets float2 at words l and 32+l
    float2 r0 = __ldcs(&self2[row * 64 + lane]);
    float2 r1 = __ldcs(&self2[row * 64 + 32 + lane]);
    a0 += r0.x; a1 += r0.y; a2 += r1.x; a3 += r1.y;

    // LayerNorm across the warp's 128 values
    float s  = a0 + a1 + a2 + a3;
    float sq = a0 * a0 + a1 * a1 + a2 * a2 + a3 * a3;
#pragma unroll
    for (int o = 16; o > 0; o >>= 1) {
        s  += __shfl_xor_sync(0xffffffffu, s,  o);
        sq += __shfl_xor_sync(0xffffffffu, sq, o);
    }
    float m    = s * (1.f / DIM);
    float var  = sq * (1.f / DIM) - m * m;
    float rstd = rsqrtf(var + LN_EPS);

    const float2* gamma2 = reinterpret_cast<const float2*>(gamma);
    const float2* beta2  = reinterpret_cast<const float2*>(beta);
    float2 g0 = __ldg(&gamma2[lane]);
    float2 g1 = __ldg(&gamma2[32 + lane]);
    float2 b0 = __ldg(&beta2 [lane]);
    float2 b1 = __ldg(&beta2 [32 + lane]);

    float2 o0, o1;
    o0.x = g0.x * (a0 - m) * rstd + b0.x;
    o0.y = g0.y * (a1 - m) * rstd + b0.y;
    o1.x = g1.x * (a2 - m) * rstd + b1.x;
    o1.y = g1.y * (a3 - m) * rstd + b1.y;
    __stcs(&out2[row * 64 + lane], o0);
    __stcs(&out2[row * 64 + 32 + lane], o1);

    if (WRITE_BF) {
        __nv_bfloat162 lo = __float22bfloat162_rn(make_float2(o0.x, o0.y));
        __nv_bfloat162 hi = __float22bfloat162_rn(make_float2(o1.x, o1.y));
        outbf[row * 64 + lane]      = *reinterpret_cast<unsigned int*>(&lo);
        outbf[row * 64 + 32 + lane] = *reinterpret_cast<unsigned int*>(&hi);
    }
}

// ---------------- launch -----------------------------------------------------
extern "C" void kernel_launch(void* const* d_in, const int* in_sizes, int n_in,
                              void* d_out, int out_size) {
    const float* user_emb = (const float*)d_in[0];
    const float* item_emb = (const float*)d_in[1];
    const float* vals     = (const float*)d_in[2];
    const float* gamma    = (const float*)d_in[3];
    const float* beta     = (const float*)d_in[4];
    const int*   rows     = (const int*)d_in[5];
    const int*   cols     = (const int*)d_in[6];

    float* out   = (float*)d_out;
    float* u_out = out;
    float* i_out = out + (size_t)NUSERS * DIM;

    void* p;
    cudaGetSymbolAddress(&p, g_u_buf);  float* u_buf = (float*)p;
    cudaGetSymbolAddress(&p, g_i_buf);  float* i_buf = (float*)p;
    cudaGetSymbolAddress(&p, g_u_bf0);  unsigned int* u_bf0 = (unsigned int*)p;
    cudaGetSymbolAddress(&p, g_i_bf0);  unsigned int* i_bf0 = (unsigned int*)p;
    cudaGetSymbolAddress(&p, g_u_bf1);  unsigned int* u_bf1 = (unsigned int*)p;
    cudaGetSymbolAddress(&p, g_i_bf1);  unsigned int* i_bf1 = (unsigned int*)p;

    const int prep_blocks  = (NITEMS * 32 + 255) / 256;              // 25000
    const int edge_blocks  = (NEDGES + 255) / 256;                   // 7813
    const int layer_blocks = ((NUSERS + NITEMS) * 32 + 255) / 256;   // 37500

    // 1: bf16 conversion + histogram (g_cnt zero on entry by invariant)
    prep_hist_kernel<<<prep_blocks, 256>>>((const float4*)user_emb,
                                           (const float4*)item_emb, rows, cols);
    // 2: reservation scan (reads g_cnt, then restores it to zero)
    reserve_kernel<<<NU_BLKS + NC_BLKS, RSV_BLK>>>();
    // 3: build AoS edge lists (restores g_total to zero)
    build_kernel<<<edge_blocks, 256>>>(rows, cols, vals);

    // 4: layer 1 (profiled slot) — selves = originals, gathers from bf0
    layer_kernel<true><<<layer_blocks, 256>>>(
        (const float2*)user_emb, (const float2*)item_emb,
        u_bf0, i_bf0, gamma, beta,
        (float2*)u_buf, (float2*)i_buf, u_bf1, i_bf1);

    // 5: layer 2 — selves = layer-1 fp32, gathers from bf1, write final out
    layer_kernel<false><<<layer_blocks, 256>>>(
        (const float2*)u_buf, (const float2*)i_buf,
        u_bf1, i_bf1, gamma, beta,
        (float2*)u_out, (float2*)i_out, nullptr, nullptr);
}